// round 3
// baseline (speedup 1.0000x reference)
#include <cuda_runtime.h>
#include <math.h>

#define NUM_LAYERS 6
#define CDIM 768
#define NHEADS 12
#define DHEAD 64
#define LATD 256
#define NTOK 65
#define BATCH 512
#define ROWS (BATCH*NTOK)          // 33280
#define C3 (3*CDIM)                // 2304
#define C4 (4*CDIM)                // 3072
#define BHD (BATCH*NHEADS)         // 6144
#define BIASN (NTOK*NTOK)          // 4225

// ---------------- scratch (static device allocations; no cudaMalloc) ----------------
__device__ float g_h   [(size_t)ROWS*CDIM];   // LN1 / LN2 output
__device__ float g_qkv [(size_t)ROWS*C3];     // qkv (q,k normalized in place)
__device__ float g_o   [(size_t)ROWS*CDIM];   // attention output, (B,N,H*DH)
__device__ float g_gated[(size_t)ROWS*C4];    // gate * silu(value)
__device__ float g_bias[(size_t)BHD*BIASN];   // attention bias (B*H, 65*65)
__device__ float g_sg1 [512*512];
__device__ float g_sg2 [512*3072];

// ---------------- helpers ----------------
__device__ __forceinline__ unsigned f2tf32(float x){
    unsigned r; asm("cvt.rna.tf32.f32 %0, %1;" : "=r"(r) : "f"(x)); return r;
}
__device__ __forceinline__ void mma_tf32(float c[4],
        unsigned a0, unsigned a1, unsigned a2, unsigned a3,
        unsigned b0, unsigned b1){
    asm volatile(
      "mma.sync.aligned.m16n8k8.row.col.f32.tf32.tf32.f32 "
      "{%0,%1,%2,%3}, {%4,%5,%6,%7}, {%8,%9}, {%0,%1,%2,%3};\n"
      : "+f"(c[0]), "+f"(c[1]), "+f"(c[2]), "+f"(c[3])
      : "r"(a0), "r"(a1), "r"(a2), "r"(a3), "r"(b0), "r"(b1));
}

// ---------------- tf32 GEMM: C[M,N] = A[M,K] @ B[K,N]  (EPI=0 store, EPI=1 += ) -------
// Requires: M % 128 == 0, K % 16 == 0, lda/acol 4-aligned. N arbitrary (guarded).
template<int EPI>
__global__ void __launch_bounds__(256)
gemm_tf32_kernel(const float* __restrict__ A, const float* __restrict__ B,
                 float* __restrict__ C, int M, int N, int K,
                 int lda, int ldb, int ldc)
{
    constexpr int BM=128, BN=128, BK=16;
    constexpr int AST=BK+4;    // 20: (20*g+q)%32 distinct for g<8,q<4
    constexpr int BST=BN+8;    // 136: (8*q+g)%32 distinct
    __shared__ float As[2][BM*AST];
    __shared__ float Bs[2][BK*BST];

    const int tid  = threadIdx.x;
    const int wid  = tid >> 5, lane = tid & 31;
    const int wm   = wid >> 2, wn   = wid & 3;      // 2 x 4 warps, warp tile 64x32
    const int g    = lane >> 2, q   = lane & 3;
    const long long bm = (long long)blockIdx.y * BM;
    const int bn   = blockIdx.x * BN;

    const int arow = tid >> 2, acol = (tid & 3) * 4;   // A: 2 x float4 per thread
    const int brow = tid >> 5, bcol = (tid & 31) * 4;  // B: 8 scalars per thread

    float acc[4][4][4];
    #pragma unroll
    for (int i=0;i<4;i++)
      #pragma unroll
      for (int j=0;j<4;j++)
        #pragma unroll
        for (int r=0;r<4;r++) acc[i][j][r]=0.f;

    float a_ld[8], b_ld[8];

    auto LOAD = [&](int kt){
        const float* Ap = A + (bm + arow)*lda + kt*BK + acol;
        float4 v0 = *(const float4*)Ap;
        float4 v1 = *(const float4*)(Ap + 64LL*lda);
        a_ld[0]=v0.x; a_ld[1]=v0.y; a_ld[2]=v0.z; a_ld[3]=v0.w;
        a_ld[4]=v1.x; a_ld[5]=v1.y; a_ld[6]=v1.z; a_ld[7]=v1.w;
        #pragma unroll
        for (int i=0;i<4;i++){
            int col = bn + bcol + i;
            bool ok = (col < N);
            b_ld[i]   = ok ? B[(long long)(kt*BK + brow    )*ldb + col] : 0.f;
            b_ld[4+i] = ok ? B[(long long)(kt*BK + brow + 8)*ldb + col] : 0.f;
        }
    };
    auto STORE_SM = [&](int s){
        #pragma unroll
        for (int i=0;i<4;i++){
            As[s][(arow   )*AST + acol + i] = __uint_as_float(f2tf32(a_ld[i]));
            As[s][(arow+64)*AST + acol + i] = __uint_as_float(f2tf32(a_ld[4+i]));
            Bs[s][(brow   )*BST + bcol + i] = __uint_as_float(f2tf32(b_ld[i]));
            Bs[s][(brow+8 )*BST + bcol + i] = __uint_as_float(f2tf32(b_ld[4+i]));
        }
    };
    auto COMPUTE = [&](int s){
        #pragma unroll
        for (int ks=0; ks<2; ks++){
            const int kk = ks*8;
            unsigned af[4][4], bf[4][2];
            #pragma unroll
            for (int i=0;i<4;i++){
                int r0 = wm*64 + i*16 + g;
                af[i][0]=__float_as_uint(As[s][(r0  )*AST + kk + q    ]);
                af[i][1]=__float_as_uint(As[s][(r0+8)*AST + kk + q    ]);
                af[i][2]=__float_as_uint(As[s][(r0  )*AST + kk + q + 4]);
                af[i][3]=__float_as_uint(As[s][(r0+8)*AST + kk + q + 4]);
            }
            #pragma unroll
            for (int j=0;j<4;j++){
                int c0 = wn*32 + j*8 + g;
                bf[j][0]=__float_as_uint(Bs[s][(kk + q    )*BST + c0]);
                bf[j][1]=__float_as_uint(Bs[s][(kk + q + 4)*BST + c0]);
            }
            #pragma unroll
            for (int i=0;i<4;i++)
              #pragma unroll
              for (int j=0;j<4;j++)
                mma_tf32(acc[i][j], af[i][0],af[i][1],af[i][2],af[i][3],
                         bf[j][0], bf[j][1]);
        }
    };

    const int ktiles = K / BK;
    LOAD(0); STORE_SM(0); __syncthreads();
    for (int t=0; t<ktiles; t++){
        int cur = t & 1;
        if (t+1 < ktiles) LOAD(t+1);
        COMPUTE(cur);
        if (t+1 < ktiles) STORE_SM(cur ^ 1);
        __syncthreads();
    }

    #pragma unroll
    for (int i=0;i<4;i++){
        long long row = bm + wm*64 + i*16 + g;
        float* Cp0 = C + row*ldc;
        float* Cp1 = C + (row+8)*ldc;
        #pragma unroll
        for (int j=0;j<4;j++){
            int col = bn + wn*32 + j*8 + q*2;
            if (col < N){
                if (EPI==0){ Cp0[col]=acc[i][j][0]; Cp1[col]=acc[i][j][2]; }
                else       { Cp0[col]+=acc[i][j][0]; Cp1[col]+=acc[i][j][2]; }
            }
            if (col+1 < N){
                if (EPI==0){ Cp0[col+1]=acc[i][j][1]; Cp1[col+1]=acc[i][j][3]; }
                else       { Cp0[col+1]+=acc[i][j][1]; Cp1[col+1]+=acc[i][j][3]; }
            }
        }
    }
}

// -------- dual GEMM: C = (A@B1) * silu(A@B2), BN=64, N%64==0, ldb%4==0 --------
__global__ void __launch_bounds__(256)
gemm_dual_tf32_kernel(const float* __restrict__ A, const float* __restrict__ B1,
                      const float* __restrict__ B2, float* __restrict__ C,
                      int M, int N, int K, int lda, int ldb, int ldc)
{
    constexpr int BM=128, BN=64, BK=16;
    constexpr int AST=BK+4;   // 20
    constexpr int BST=BN+8;   // 72
    __shared__ float As [2][BM*AST];
    __shared__ float B1s[2][BK*BST];
    __shared__ float B2s[2][BK*BST];

    const int tid  = threadIdx.x;
    const int wid  = tid >> 5, lane = tid & 31;
    const int wm   = wid >> 2, wn   = wid & 3;      // 2 x 4 warps, warp tile 64x16
    const int g    = lane >> 2, q   = lane & 3;
    const long long bm = (long long)blockIdx.y * BM;
    const int bn   = blockIdx.x * BN;

    const int arow = tid >> 2, acol = (tid & 3) * 4;
    const int brow = tid >> 4, bcol = (tid & 15) * 4;  // 16x64, one float4 per matrix

    float accg[4][2][4], accv[4][2][4];
    #pragma unroll
    for (int i=0;i<4;i++)
      #pragma unroll
      for (int j=0;j<2;j++)
        #pragma unroll
        for (int r=0;r<4;r++){ accg[i][j][r]=0.f; accv[i][j][r]=0.f; }

    float a_ld[8]; float4 b1_ld, b2_ld;

    auto LOAD = [&](int kt){
        const float* Ap = A + (bm + arow)*lda + kt*BK + acol;
        float4 v0 = *(const float4*)Ap;
        float4 v1 = *(const float4*)(Ap + 64LL*lda);
        a_ld[0]=v0.x; a_ld[1]=v0.y; a_ld[2]=v0.z; a_ld[3]=v0.w;
        a_ld[4]=v1.x; a_ld[5]=v1.y; a_ld[6]=v1.z; a_ld[7]=v1.w;
        long long off = (long long)(kt*BK + brow)*ldb + bn + bcol;
        b1_ld = *(const float4*)(B1 + off);
        b2_ld = *(const float4*)(B2 + off);
    };
    auto STORE_SM = [&](int s){
        #pragma unroll
        for (int i=0;i<4;i++){
            As[s][(arow   )*AST + acol + i] = __uint_as_float(f2tf32(a_ld[i]));
            As[s][(arow+64)*AST + acol + i] = __uint_as_float(f2tf32(a_ld[4+i]));
        }
        float b1v[4] = {b1_ld.x,b1_ld.y,b1_ld.z,b1_ld.w};
        float b2v[4] = {b2_ld.x,b2_ld.y,b2_ld.z,b2_ld.w};
        #pragma unroll
        for (int i=0;i<4;i++){
            B1s[s][brow*BST + bcol + i] = __uint_as_float(f2tf32(b1v[i]));
            B2s[s][brow*BST + bcol + i] = __uint_as_float(f2tf32(b2v[i]));
        }
    };
    auto COMPUTE = [&](int s){
        #pragma unroll
        for (int ks=0; ks<2; ks++){
            const int kk = ks*8;
            unsigned af[4][4], bf1[2][2], bf2[2][2];
            #pragma unroll
            for (int i=0;i<4;i++){
                int r0 = wm*64 + i*16 + g;
                af[i][0]=__float_as_uint(As[s][(r0  )*AST + kk + q    ]);
                af[i][1]=__float_as_uint(As[s][(r0+8)*AST + kk + q    ]);
                af[i][2]=__float_as_uint(As[s][(r0  )*AST + kk + q + 4]);
                af[i][3]=__float_as_uint(As[s][(r0+8)*AST + kk + q + 4]);
            }
            #pragma unroll
            for (int j=0;j<2;j++){
                int c0 = wn*16 + j*8 + g;
                bf1[j][0]=__float_as_uint(B1s[s][(kk + q    )*BST + c0]);
                bf1[j][1]=__float_as_uint(B1s[s][(kk + q + 4)*BST + c0]);
                bf2[j][0]=__float_as_uint(B2s[s][(kk + q    )*BST + c0]);
                bf2[j][1]=__float_as_uint(B2s[s][(kk + q + 4)*BST + c0]);
            }
            #pragma unroll
            for (int i=0;i<4;i++)
              #pragma unroll
              for (int j=0;j<2;j++){
                mma_tf32(accg[i][j], af[i][0],af[i][1],af[i][2],af[i][3], bf1[j][0], bf1[j][1]);
                mma_tf32(accv[i][j], af[i][0],af[i][1],af[i][2],af[i][3], bf2[j][0], bf2[j][1]);
              }
        }
    };

    const int ktiles = K / BK;
    LOAD(0); STORE_SM(0); __syncthreads();
    for (int t=0; t<ktiles; t++){
        int cur = t & 1;
        if (t+1 < ktiles) LOAD(t+1);
        COMPUTE(cur);
        if (t+1 < ktiles) STORE_SM(cur ^ 1);
        __syncthreads();
    }

    #pragma unroll
    for (int i=0;i<4;i++){
        long long row = bm + wm*64 + i*16 + g;
        float* Cp0 = C + row*ldc;
        float* Cp1 = C + (row+8)*ldc;
        #pragma unroll
        for (int j=0;j<2;j++){
            int col = bn + wn*16 + j*8 + q*2;
            #pragma unroll
            for (int r=0;r<4;r++){
                float gg = accg[i][j][r];
                float vv = accv[i][j][r];
                float out = gg * (vv / (1.f + expf(-vv)));
                float* Cp = (r < 2) ? Cp0 : Cp1;
                Cp[col + (r & 1)] = out;
            }
        }
    }
}

// ---------------- LayerNorm (one row per block, 256 threads) ----------------
__global__ void ln_kernel(const float* __restrict__ in, float* __restrict__ out,
                          const float* __restrict__ gamma, const float* __restrict__ beta,
                          int W, int dosilu)
{
    long long row = blockIdx.x;
    const float* x = in + row*(long long)W;
    float* y = out + row*(long long)W;
    float s=0.f, s2=0.f;
    for (int i=threadIdx.x; i<W; i+=blockDim.x){ float v=x[i]; s+=v; s2+=v*v; }
    __shared__ float rs[32], rs2[32];
    int lane = threadIdx.x & 31, wid = threadIdx.x >> 5;
    #pragma unroll
    for (int o=16;o;o>>=1){ s += __shfl_xor_sync(0xffffffffu,s,o); s2 += __shfl_xor_sync(0xffffffffu,s2,o); }
    if (lane==0){ rs[wid]=s; rs2[wid]=s2; }
    __syncthreads();
    if (wid==0){
        float a  = (lane<8)? rs[lane]  : 0.f;
        float a2 = (lane<8)? rs2[lane] : 0.f;
        #pragma unroll
        for (int o=4;o;o>>=1){ a += __shfl_xor_sync(0xffffffffu,a,o); a2 += __shfl_xor_sync(0xffffffffu,a2,o); }
        if (lane==0){ rs[0]=a; rs2[0]=a2; }
    }
    __syncthreads();
    float mean = rs[0]/(float)W;
    float var  = rs2[0]/(float)W - mean*mean;
    float rstd = rsqrtf(var + 1e-5f);
    for (int i=threadIdx.x; i<W; i+=blockDim.x){
        float v = (x[i]-mean)*rstd*gamma[i] + beta[i];
        if (dosilu) v = v / (1.f + expf(-v));
        y[i] = v;
    }
}

// ---------------- QK LayerNorm over DH=64 (one warp per (row, q/k, head)) -----------
__global__ void qknorm_kernel(float* __restrict__ qkv,
                              const float* __restrict__ qg, const float* __restrict__ qb,
                              const float* __restrict__ kg, const float* __restrict__ kb)
{
    int w = (blockIdx.x*blockDim.x + threadIdx.x) >> 5;
    int lane = threadIdx.x & 31;
    if (w >= ROWS*24) return;
    int r = w / 24, rem = w % 24, t = rem / 12, h = rem % 12;
    float* p = qkv + (long long)r*C3 + t*CDIM + h*DHEAD;
    float v0 = p[lane], v1 = p[lane+32];
    float s = v0 + v1;
    #pragma unroll
    for (int o=16;o;o>>=1) s += __shfl_xor_sync(0xffffffffu,s,o);
    float mean = s * (1.f/64.f);
    float d0 = v0-mean, d1 = v1-mean;
    float s2 = d0*d0 + d1*d1;
    #pragma unroll
    for (int o=16;o;o>>=1) s2 += __shfl_xor_sync(0xffffffffu,s2,o);
    float rstd = rsqrtf(s2*(1.f/64.f) + 1e-5f);
    const float* gg = t ? kg : qg;
    const float* bb = t ? kb : qb;
    float scale = t ? 1.f : 0.125f;   // DH^-0.5 applied to q
    p[lane]    = (d0*rstd*gg[lane]    + bb[lane]   ) * scale;
    p[lane+32] = (d1*rstd*gg[lane+32] + bb[lane+32]) * scale;
}

// ---------------- fused attention per (b,h): S=qk^T+bias, softmax, O=S@v ------------
__global__ void __launch_bounds__(256)
attn_kernel(const float* __restrict__ qkv, const float* __restrict__ bias,
            float* __restrict__ o)
{
    int bh = blockIdx.x;
    int b  = bh / NHEADS, hh = bh % NHEADS;
    extern __shared__ float sm[];
    float* qs = sm;                     // 65*64
    float* kt = qs + NTOK*DHEAD;        // 64*65 (transposed: kt[d*65+j])
    float* vs = kt + DHEAD*NTOK;        // 65*64
    float* S  = vs + NTOK*DHEAD;        // 65*65
    int tid = threadIdx.x;

    for (int idx=tid; idx<NTOK*DHEAD; idx+=256){
        int n = idx >> 6, d = idx & 63;
        const float* base = qkv + (long long)(b*NTOK+n)*C3 + hh*DHEAD + d;
        qs[idx]        = base[0];
        kt[d*NTOK + n] = base[CDIM];
        vs[idx]        = base[2*CDIM];
    }
    __syncthreads();

    const float* bb = bias + (long long)bh*BIASN;
    for (int idx=tid; idx<NTOK*NTOK; idx+=256){
        int i = idx / NTOK, j = idx - i*NTOK;
        float acc = bb[idx];
        const float* qr = qs + i*DHEAD;
        #pragma unroll 16
        for (int d=0; d<DHEAD; d++) acc += qr[d]*kt[d*NTOK + j];
        S[idx] = acc;
    }
    __syncthreads();

    int wid = tid >> 5, lane = tid & 31;
    for (int i=wid; i<NTOK; i+=8){
        float* Sr = S + i*NTOK;
        float m = -1e30f;
        for (int j=lane; j<NTOK; j+=32) m = fmaxf(m, Sr[j]);
        #pragma unroll
        for (int off=16;off;off>>=1) m = fmaxf(m, __shfl_xor_sync(0xffffffffu,m,off));
        float sum = 0.f;
        for (int j=lane; j<NTOK; j+=32){ float e = expf(Sr[j]-m); Sr[j]=e; sum+=e; }
        #pragma unroll
        for (int off=16;off;off>>=1) sum += __shfl_xor_sync(0xffffffffu,sum,off);
        float inv = 1.f/sum;
        for (int j=lane; j<NTOK; j+=32) Sr[j] *= inv;
    }
    __syncthreads();

    for (int idx=tid; idx<NTOK*DHEAD; idx+=256){
        int i = idx >> 6, d = idx & 63;
        float acc = 0.f;
        const float* Sr = S + i*NTOK;
        #pragma unroll 13
        for (int j=0; j<NTOK; j++) acc += Sr[j]*vs[j*DHEAD + d];
        o[(long long)(b*NTOK+i)*CDIM + hh*DHEAD + d] = acc;
    }
}

// ---------------- host ----------------
extern "C" void kernel_launch(void* const* d_in, const int* in_sizes, int n_in,
                              void* d_out, int out_size)
{
    (void)in_sizes; (void)n_in; (void)out_size;
    const float* ln1_g  = (const float*)d_in[1];
    const float* ln1_b  = (const float*)d_in[2];
    const float* qkv_w  = (const float*)d_in[3];
    const float* proj_w = (const float*)d_in[4];
    const float* qn_g   = (const float*)d_in[5];
    const float* qn_b   = (const float*)d_in[6];
    const float* kn_g   = (const float*)d_in[7];
    const float* kn_b   = (const float*)d_in[8];
    const float* sg_w1  = (const float*)d_in[9];
    const float* sg1g   = (const float*)d_in[10];
    const float* sg1b   = (const float*)d_in[11];
    const float* sg_w2  = (const float*)d_in[12];
    const float* sg2g   = (const float*)d_in[13];
    const float* sg2b   = (const float*)d_in[14];
    const float* bw     = (const float*)d_in[15];
    const float* ln2_g  = (const float*)d_in[16];
    const float* ln2_b  = (const float*)d_in[17];
    const float* gate_w = (const float*)d_in[18];
    const float* value_w= (const float*)d_in[19];
    const float* out_w  = (const float*)d_in[20];

    float* X = (float*)d_out;

    void *ph, *pqkv, *po, *pgated, *pbias, *psg1, *psg2;
    cudaGetSymbolAddress(&ph,    g_h);
    cudaGetSymbolAddress(&pqkv,  g_qkv);
    cudaGetSymbolAddress(&po,    g_o);
    cudaGetSymbolAddress(&pgated,g_gated);
    cudaGetSymbolAddress(&pbias, g_bias);
    cudaGetSymbolAddress(&psg1,  g_sg1);
    cudaGetSymbolAddress(&psg2,  g_sg2);
    float* h     = (float*)ph;
    float* qkv   = (float*)pqkv;
    float* o     = (float*)po;
    float* gated = (float*)pgated;
    float* bias  = (float*)pbias;
    float* sg1   = (float*)psg1;
    float* sg2   = (float*)psg2;

    const int attn_smem = (NTOK*DHEAD + DHEAD*NTOK + NTOK*DHEAD + NTOK*NTOK) * 4;
    cudaFuncSetAttribute(attn_kernel, cudaFuncAttributeMaxDynamicSharedMemorySize, attn_smem);

    // x -> running residual stream in d_out
    cudaMemcpyAsync(X, d_in[0], sizeof(float)*(size_t)ROWS*CDIM, cudaMemcpyDeviceToDevice);

    for (int l=0; l<NUM_LAYERS; l++){
        // h = LN1(x)
        ln_kernel<<<ROWS,256>>>(X, h, ln1_g + (size_t)l*CDIM, ln1_b + (size_t)l*CDIM, CDIM, 0);
        // qkv = h @ qkv_w
        gemm_tf32_kernel<0><<<dim3(C3/128, ROWS/128), 256>>>(
            h, qkv_w + (size_t)l*CDIM*C3, qkv, ROWS, C3, CDIM, CDIM, C3, C3);
        // q,k norm (+q scale) in place
        qknorm_kernel<<<(ROWS*24)/8, 256>>>(qkv,
            qn_g + (size_t)l*DHEAD, qn_b + (size_t)l*DHEAD,
            kn_g + (size_t)l*DHEAD, kn_b + (size_t)l*DHEAD);
        // structure-gate bias MLP (cls rows of h, lda = N*C)
        gemm_tf32_kernel<0><<<dim3(4,4), 256>>>(
            h, sg_w1 + (size_t)l*CDIM*512, sg1, 512, 512, CDIM, NTOK*CDIM, 512, 512);
        ln_kernel<<<512,256>>>(sg1, sg1, sg1g + (size_t)l*512, sg1b + (size_t)l*512, 512, 1);
        gemm_tf32_kernel<0><<<dim3(24,4), 256>>>(
            sg1, sg_w2 + (size_t)l*512*3072, sg2, 512, 3072, 512, 512, 3072, 3072);
        ln_kernel<<<512,256>>>(sg2, sg2, sg2g + (size_t)l*3072, sg2b + (size_t)l*3072, 3072, 0);
        // bias = lat2(B*H,256) @ bw(256,4225)
        gemm_tf32_kernel<0><<<dim3((BIASN+127)/128, BHD/128), 256>>>(
            sg2, bw + (size_t)l*LATD*BIASN, bias, BHD, BIASN, LATD, LATD, BIASN, BIASN);
        // fused attention
        attn_kernel<<<BHD, 256, attn_smem>>>(qkv, bias, o);
        // x += o @ proj_w
        gemm_tf32_kernel<1><<<dim3(CDIM/128, ROWS/128), 256>>>(
            o, proj_w + (size_t)l*CDIM*CDIM, X, ROWS, CDIM, CDIM, CDIM, CDIM, CDIM);
        // h2 = LN2(x)
        ln_kernel<<<ROWS,256>>>(X, h, ln2_g + (size_t)l*CDIM, ln2_b + (size_t)l*CDIM, CDIM, 0);
        // gated = (h2@gate_w) * silu(h2@value_w)
        gemm_dual_tf32_kernel<<<dim3(C4/64, ROWS/128), 256>>>(
            h, gate_w + (size_t)l*CDIM*C4, value_w + (size_t)l*CDIM*C4, gated,
            ROWS, C4, CDIM, CDIM, C4, C4);
        // x += gated @ out_w
        gemm_tf32_kernel<1><<<dim3(CDIM/128, ROWS/128), 256>>>(
            gated, out_w + (size_t)l*C4*CDIM, X, ROWS, CDIM, C4, C4, CDIM, CDIM);
    }
}